// round 1
// baseline (speedup 1.0000x reference)
#include <cuda_runtime.h>
#include <cstdint>

#define BATCH 4
#define NPTS  4096
#define DIM   512
#define K_NB  10

#define ROWS_PER_BLOCK 32
#define COLS_PER_TILE  128
#define KCHUNK         32

// Scratch (no device allocation allowed in kernel_launch):
__device__ __align__(16) float g_Hn[BATCH * NPTS * DIM];       // 32 MB normalized H
__device__ int g_topk[BATCH * NPTS * K_NB];                    // top-10 indices per row

// ---------------------------------------------------------------------------
// Kernel 1: row-normalize H -> g_Hn  (one warp per row)
// ---------------------------------------------------------------------------
__global__ void normalize_kernel(const float* __restrict__ H) {
    int warp = (blockIdx.x * blockDim.x + threadIdx.x) >> 5;
    int lane = threadIdx.x & 31;
    if (warp >= BATCH * NPTS) return;
    const float4* src = (const float4*)(H + (size_t)warp * DIM);
    float4* dst = (float4*)(g_Hn + (size_t)warp * DIM);
    float ss = 0.f;
    float4 v[4];
#pragma unroll
    for (int j = 0; j < 4; j++) {
        v[j] = src[lane + 32 * j];
        ss += v[j].x * v[j].x + v[j].y * v[j].y + v[j].z * v[j].z + v[j].w * v[j].w;
    }
#pragma unroll
    for (int o = 16; o; o >>= 1) ss += __shfl_xor_sync(0xffffffffu, ss, o);
    float nrm = fmaxf(sqrtf(ss), 1e-12f);
    float inv = 1.0f / nrm;
#pragma unroll
    for (int j = 0; j < 4; j++) {
        v[j].x *= inv; v[j].y *= inv; v[j].z *= inv; v[j].w *= inv;
        dst[lane + 32 * j] = v[j];
    }
}

// ---------------------------------------------------------------------------
// Kernel 2: fused fp32 GEMM (sim tile) + streaming per-row top-10
//   grid = (NPTS/ROWS_PER_BLOCK, BATCH), 256 threads (8 warps)
//   each warp owns 4 rows; lane micro-tile = 4 rows x 4 cols of a 128-col tile
// ---------------------------------------------------------------------------
__device__ __forceinline__ bool beats(float v, int vi, float w, int wi) {
    return (v > w) || (v == w && vi < wi);
}

__global__ void __launch_bounds__(256) simtopk_kernel() {
    __shared__ __align__(16) float As[KCHUNK][36];    // [k][row], padded
    __shared__ __align__(16) float Bs[KCHUNK][132];   // [k][col], padded
    __shared__ float s_val[ROWS_PER_BLOCK][K_NB];     // sorted ascending (min at [0])
    __shared__ int   s_idx[ROWS_PER_BLOCK][K_NB];

    const int b = blockIdx.y;
    const int rowBase = blockIdx.x * ROWS_PER_BLOCK;
    const int tid = threadIdx.x;
    const int warp = tid >> 5, lane = tid & 31;

    for (int i = tid; i < ROWS_PER_BLOCK * K_NB; i += 256) {
        ((float*)s_val)[i] = -3.0e38f;
        ((int*)s_idx)[i] = 0x7fffffff;
    }
    __syncthreads();

    const float* __restrict__ Hb = g_Hn + (size_t)b * NPTS * DIM;

    for (int ct = 0; ct < NPTS; ct += COLS_PER_TILE) {
        float acc[4][4];
#pragma unroll
        for (int r = 0; r < 4; r++)
#pragma unroll
            for (int c = 0; c < 4; c++) acc[r][c] = 0.f;

        for (int kc = 0; kc < DIM; kc += KCHUNK) {
            // stage A chunk transposed: 32 rows x 32 k
            {
                int r = tid >> 3;               // 0..31
                int k0 = (tid & 7) * 4;         // 0..28
                float4 a = *(const float4*)(Hb + (size_t)(rowBase + r) * DIM + kc + k0);
                As[k0 + 0][r] = a.x; As[k0 + 1][r] = a.y;
                As[k0 + 2][r] = a.z; As[k0 + 3][r] = a.w;
            }
            // stage B chunk transposed: 128 cols x 32 k (16 floats per thread)
            {
                int c = tid >> 1;               // 0..127
                int kb = (tid & 1) * 16;        // 0 or 16
                const float* src = Hb + (size_t)(ct + c) * DIM + kc + kb;
#pragma unroll
                for (int j = 0; j < 4; j++) {
                    float4 v = *(const float4*)(src + 4 * j);
                    Bs[kb + 4 * j + 0][c] = v.x; Bs[kb + 4 * j + 1][c] = v.y;
                    Bs[kb + 4 * j + 2][c] = v.z; Bs[kb + 4 * j + 3][c] = v.w;
                }
            }
            __syncthreads();
#pragma unroll
            for (int k = 0; k < KCHUNK; k++) {
                float4 av = *(const float4*)(&As[k][warp * 4]);   // broadcast
                float4 bv = *(const float4*)(&Bs[k][lane * 4]);
                float ar[4] = {av.x, av.y, av.z, av.w};
                float br[4] = {bv.x, bv.y, bv.z, bv.w};
#pragma unroll
                for (int r = 0; r < 4; r++)
#pragma unroll
                    for (int c = 0; c < 4; c++)
                        acc[r][c] = fmaf(ar[r], br[c], acc[r][c]);
            }
            __syncthreads();
        }

        // fold 128-col tile into per-row top-10 (warp-local, rare insertions)
#pragma unroll
        for (int r = 0; r < 4; r++) {
            const int rowL = warp * 4 + r;
#pragma unroll
            for (int c = 0; c < 4; c++) {
                float v = acc[r][c];
                int col = ct + lane * 4 + c;
                float tv = s_val[rowL][0];
                int ti = s_idx[rowL][0];
                unsigned m = __ballot_sync(0xffffffffu, beats(v, col, tv, ti));
                while (m) {
                    int src = __ffs(m) - 1;
                    m &= m - 1;
                    float cv = __shfl_sync(0xffffffffu, v, src);
                    int ci = __shfl_sync(0xffffffffu, col, src);
                    if (lane == 0) {
                        float* lv = s_val[rowL];
                        int* li = s_idx[rowL];
                        if (beats(cv, ci, lv[0], li[0])) {
                            int j = 0;
                            while (j < K_NB - 1 && beats(cv, ci, lv[j + 1], li[j + 1])) {
                                lv[j] = lv[j + 1]; li[j] = li[j + 1]; j++;
                            }
                            lv[j] = cv; li[j] = ci;
                        }
                    }
                    __syncwarp();
                }
            }
        }
    }
    __syncthreads();

    for (int i = tid; i < ROWS_PER_BLOCK * K_NB; i += 256) {
        int r = i / K_NB, k = i % K_NB;
        g_topk[((size_t)b * NPTS + rowBase + r) * K_NB + k] = s_idx[r][k];
    }
}

// ---------------------------------------------------------------------------
// Kernel 3: zero the output (poisoned 0xAA by the harness)
// ---------------------------------------------------------------------------
__global__ void zero_kernel(float4* __restrict__ out, size_t n4) {
    size_t i = (size_t)blockIdx.x * blockDim.x + threadIdx.x;
    size_t stride = (size_t)gridDim.x * blockDim.x;
    float4 z = make_float4(0.f, 0.f, 0.f, 0.f);
    for (; i < n4; i += stride) out[i] = z;
}

// ---------------------------------------------------------------------------
// Kernel 4: scatter s = 1/11 at top-k positions, add s at diagonal
// ---------------------------------------------------------------------------
__global__ void scatter_kernel(float* __restrict__ out) {
    int row = blockIdx.x * blockDim.x + threadIdx.x;
    if (row >= BATCH * NPTS) return;
    int i = row & (NPTS - 1);
    float* dst = out + (size_t)row * NPTS;
    const int* idx = g_topk + (size_t)row * K_NB;
    const float s = 1.0f / 11.0f;
#pragma unroll
    for (int k = 0; k < K_NB; k++) dst[idx[k]] = s;
    dst[i] += s;   // eye; yields 2s when i is in its own top-k (it always is)
}

// ---------------------------------------------------------------------------
extern "C" void kernel_launch(void* const* d_in, const int* in_sizes, int n_in,
                              void* d_out, int out_size) {
    const float* H = (const float*)d_in[0];
    float* out = (float*)d_out;

    // K1: normalize (16384 warps)
    normalize_kernel<<<(BATCH * NPTS * 32 + 255) / 256, 256>>>(H);

    // K2: fused sim GEMM + top-10
    dim3 g2(NPTS / ROWS_PER_BLOCK, BATCH);
    simtopk_kernel<<<g2, 256>>>();

    // K3: zero 4*4096*4096 floats
    size_t n4 = (size_t)BATCH * NPTS * NPTS / 4;
    zero_kernel<<<16384, 256>>>((float4*)out, n4);

    // K4: scatter
    scatter_kernel<<<(BATCH * NPTS + 255) / 256, 256>>>(out);
}